// round 13
// baseline (speedup 1.0000x reference)
#include <cuda_runtime.h>
#include <math.h>

#define BQ 128
#define TQ 1024
#define IQ 128
#define HQ 512
#define G4 2048
#define BT (BQ*TQ)
#define MAXLEV 16

#define BM 64
#define BN 128
#define BKC 32
#define ES_STR 132
// Fragment-permuted SMEM layouts:
// AF[rb16][k8][lane][4] at SM[0..2048)   : ((rb16*4+k8)*32+lane)*4+f
// BF[nt][k8][lane][2]   at SM[2048..6144): ((nt*4+k8)*32+lane)*2+f
// Es[64][132]           at SM[0..8448)   (after mainloop, fenced by syncthreads)
#define BF_OFF 2048

// Static scratch (allocation-free rule: __device__ globals)
static __device__ float g_pre[(size_t)BT * G4];
static __device__ float g_H[(size_t)BT * HQ];
static __device__ float g_C[(size_t)BT * HQ];
static __device__ int   g_emit[BT];
static __device__ unsigned char g_m[BT];
static __device__ int   g_lvlcount[MAXLEV + 1];
static __device__ int   g_lvllist[(size_t)(MAXLEV + 1) * BT];
static __device__ int   g_workcount;
static __device__ int   g_work[BT];

__device__ __forceinline__ float sigf(float v) { return 1.0f / (1.0f + expf(-v)); }

__device__ __forceinline__ float tf32r(float f) {
  unsigned u; asm("cvt.rna.tf32.f32 %0, %1;" : "=r"(u) : "f"(f));
  return __uint_as_float(u);
}
__device__ __forceinline__ void mma8(float* c, const unsigned* a, const unsigned* b) {
  asm volatile(
    "mma.sync.aligned.m16n8k8.row.col.f32.tf32.tf32.f32 "
    "{%0,%1,%2,%3},{%4,%5,%6,%7},{%8,%9},{%0,%1,%2,%3};\n"
    : "+f"(c[0]), "+f"(c[1]), "+f"(c[2]), "+f"(c[3])
    : "r"(a[0]), "r"(a[1]), "r"(a[2]), "r"(a[3]), "r"(b[0]), "r"(b[1]));
}

__global__ void k_init() {
  int i = blockIdx.x * blockDim.x + threadIdx.x;
  if (i < BT) g_emit[i] = -1;
  if (i <= MAXLEV) g_lvlcount[i] = 0;
  if (i == 0) g_workcount = 0;
}

__global__ void k_row(const int* __restrict__ mask, const int* __restrict__ length,
                      float* __restrict__ out, int K, int has_wn) {
  __shared__ unsigned char ml[TQ];
  int b = blockIdx.x;
  int len = length[b];
  for (int t = threadIdx.x; t < TQ; t += 32) {
    int mv = (mask[b*TQ + t] != 0) ? 1 : 0;
    if (t == 0) mv = 0;
    if (t == len - 1) mv = 1;
    ml[t] = (unsigned char)mv;
    g_m[b*TQ + t] = (unsigned char)mv;
  }
  __syncthreads();
  if (threadIdx.x != 0) return;

  int wn = 0, lvl = 0;
  for (int t = 0; t < TQ; t++) {
    if (ml[t]) {
      wn++; lvl++;
      int L = lvl < MAXLEV ? lvl : MAXLEV;
      int idx = atomicAdd(&g_lvlcount[L], 1);
      g_lvllist[(size_t)L * BT + idx] = b*TQ + t;
    } else lvl = 0;
  }
  int need = K - wn;
  int cut = TQ;
  if (need > 0) {
    int cnt = 0;
    for (int t = TQ - 1; t >= 0; t--) {
      if (!ml[t]) { cnt++; if (cnt == need) { cut = t; break; } }
    }
  }
  int k = 0;
  for (int t = 0; t < TQ && k < K; t++) {
    if (ml[t] || t >= cut) {
      int flat = b*TQ + t - 1;
      if (flat < 0) flat += BT;
      g_emit[flat] = b*K + k;
      k++;
    }
  }
  if (has_wn) out[(size_t)BQ * (size_t)K * HQ + b] = (float)wn;
}

__global__ void k_work() {
  int p = blockIdx.x * blockDim.x + threadIdx.x;
  if (p >= BT) return;
  bool need = g_m[p] || ((p + 1 < BT) && g_m[p + 1]) || (g_emit[p] >= 0);
  if (need) {
    int idx = atomicAdd(&g_workcount, 1);
    g_work[idx] = p;
  }
}

// Stage a row-chunk of A (8 k-values) into fragment-permuted layout.
__device__ __forceinline__ void stage_a(float* SM, const float* src, int row, int q) {
  float4 v0 = ((const float4*)src)[0];
  float4 v1 = ((const float4*)src)[1];
  float vv[8] = {v0.x,v0.y,v0.z,v0.w,v1.x,v1.y,v1.z,v1.w};
  int g8r = row & 7, r8 = (row >> 3) & 1, rb16 = row >> 4;
  float* abase = SM + rb16*512 + q*128 + g8r*16 + r8;
  #pragma unroll
  for (int h = 0; h < 8; h++) {
    int tg = h & 3, kh = h >> 2;
    abase[tg*4 + kh*2] = tf32r(vv[h]);
  }
}

// Stage a column-chunk of B (16 k-values) into fragment-permuted layout.
__device__ __forceinline__ void stage_b(float* SM, const float* src, int c, int half) {
  int nt = c >> 3, g8c = c & 7;
  float* bbase = SM + BF_OFF + nt*256 + g8c*8;
  #pragma unroll
  for (int h4 = 0; h4 < 4; h4++) {
    float4 v = ((const float4*)src)[h4];
    float vv[4] = {v.x,v.y,v.z,v.w};
    #pragma unroll
    for (int e = 0; e < 4; e++) {
      int k = half*16 + h4*4 + e;
      int k8 = k >> 3, kin = k & 7, tg = kin & 3, f = kin >> 2;
      bbase[k8*64 + tg*2 + f] = tf32r(vv[e]);
    }
  }
}

__device__ __forceinline__ void mma_block(const float* SM, float acc[2][4][4],
                                          int wm, int wn, int lane) {
  #pragma unroll
  for (int k8 = 0; k8 < 4; k8++) {
    unsigned a[2][4], b[4][2];
    #pragma unroll
    for (int mi = 0; mi < 2; mi++) {
      int rb16 = wm*2 + mi;
      float4 av = *(const float4*)(SM + rb16*512 + k8*128 + lane*4);
      a[mi][0]=__float_as_uint(av.x); a[mi][1]=__float_as_uint(av.y);
      a[mi][2]=__float_as_uint(av.z); a[mi][3]=__float_as_uint(av.w);
    }
    #pragma unroll
    for (int ni = 0; ni < 4; ni++) {
      int nt = wn*4 + ni;
      float2 bv = *(const float2*)(SM + BF_OFF + nt*256 + k8*64 + lane*2);
      b[ni][0]=__float_as_uint(bv.x); b[ni][1]=__float_as_uint(bv.y);
    }
    #pragma unroll
    for (int mi = 0; mi < 2; mi++)
      #pragma unroll
      for (int ni = 0; ni < 4; ni++)
        mma8(acc[mi][ni], a[mi], b[ni]);
  }
}

__device__ __forceinline__ void dump_es(float* Es, const float acc[2][4][4],
                                        int wm, int wn, int g8, int tg) {
  #pragma unroll
  for (int mi = 0; mi < 2; mi++) {
    int r0 = wm*32 + mi*16 + g8;
    #pragma unroll
    for (int ni = 0; ni < 4; ni++) {
      int c0 = wn*32 + ni*8 + 2*tg;
      Es[ r0   *ES_STR + c0  ] = acc[mi][ni][0];
      Es[ r0   *ES_STR + c0+1] = acc[mi][ni][1];
      Es[(r0+8)*ES_STR + c0  ] = acc[mi][ni][2];
      Es[(r0+8)*ES_STR + c0+1] = acc[mi][ni][3];
    }
  }
}

// Phase 1: gates_x = x @ W_ih^T + b over worklist positions (tf32 tensor MMA).
__global__ __launch_bounds__(256) void k_main(
    const float* __restrict__ x, const int* __restrict__ length,
    const float* __restrict__ W_ih, const float* __restrict__ b_ih,
    const float* __restrict__ b_hh, float* __restrict__ out) {
  __shared__ __align__(16) float SM[8448];
  __shared__ __align__(16) float Bb[BN];
  __shared__ int plist[BM];
  float* Es = SM;

  int count = g_workcount;
  int nmt = (count + BM - 1) / BM;
  int hbase = blockIdx.y * 32;
  int tid = threadIdx.x;
  int wid = tid >> 5, lane = tid & 31;
  int wm = wid & 1, wn = wid >> 1;
  int g8 = lane >> 2, tg = lane & 3;

  if (tid < BN) {
    int c = tid;
    int j = (c & 3)*HQ + hbase + (c >> 2);
    Bb[c] = __ldg(&b_ih[j]) + __ldg(&b_hh[j]);
  }

  for (int mt = blockIdx.x; mt < nmt; mt += gridDim.x) {
    __syncthreads();
    if (tid < BM) {
      int idx = mt*BM + tid;
      plist[tid] = (idx < count) ? g_work[idx] : -1;
    }
    __syncthreads();

    float acc[2][4][4];
    #pragma unroll
    for (int i = 0; i < 2; i++)
      #pragma unroll
      for (int j = 0; j < 4; j++)
        #pragma unroll
        for (int q = 0; q < 4; q++) acc[i][j][q] = 0.0f;

    #pragma unroll
    for (int kc = 0; kc < IQ; kc += BKC) {
      {
        int row = tid >> 2, q = tid & 3;
        int p = plist[row]; if (p < 0) p = 0;
        stage_a(SM, x + (size_t)p*IQ + kc + q*8, row, q);
      }
      {
        int c = tid >> 1, half = tid & 1;
        int j = (c & 3)*HQ + hbase + (c >> 2);
        stage_b(SM, W_ih + (size_t)j*IQ + kc + half*16, c, half);
      }
      __syncthreads();
      mma_block(SM, acc, wm, wn, lane);
      __syncthreads();
    }

    dump_es(Es, acc, wm, wn, g8, tg);
    __syncthreads();

    // epilogue: 64 rows x 32 h-units; u = lane -> one float4 per lane, conflict-free
    #pragma unroll
    for (int it = 0; it < 8; it++) {
      int item = it*256 + tid;
      int r = item >> 5, u = item & 31;
      int p = plist[r];
      if (p < 0) continue;
      int hu = hbase + u;
      float4 gv = *(const float4*)(Es + r*ES_STR + 4*u);
      float4 bv = *(const float4*)(Bb + 4*u);
      float vi = gv.x + bv.x;
      float vf = gv.y + bv.y;
      float vg = gv.z + bv.z;
      float vo = gv.w + bv.w;
      if (g_m[p]) {
        size_t pb = (size_t)p*G4 + hu;
        g_pre[pb + 0*HQ] = vi;
        g_pre[pb + 1*HQ] = vf;
        g_pre[pb + 2*HQ] = vg;
        g_pre[pb + 3*HQ] = vo;
      } else {
        int t = p & (TQ-1);
        int len = __ldg(&length[p >> 10]);
        float a = (t < len) ? 1.0f : 0.0f;
        int sf = (p + 1 < BT) ? (int)g_m[p+1] : 0;
        int em = g_emit[p];
        if (!sf && em < 0) continue;
        float c2 = sigf(vi) * tanhf(vg);
        float h2 = sigf(vo) * tanhf(c2);
        float hv = a * h2;
        if (sf) {
          g_H[(size_t)p*HQ + hu] = hv;
          g_C[(size_t)p*HQ + hu] = a * c2;
        }
        if (em >= 0) out[(size_t)em*HQ + hu] = hv;
      }
    }
  }
}

// Level pass L: gates = pre + h_{t-1} @ W_hh^T (tf32 tensor MMA)
__global__ __launch_bounds__(256) void k_level(
    const float* __restrict__ W_hh, const int* __restrict__ length,
    float* __restrict__ out, int L) {
  __shared__ __align__(16) float SM[8448];
  __shared__ int plist[BM];
  float* Es = SM;

  int count = g_lvlcount[L];
  if (count == 0) return;
  int nmt = (count + BM - 1) / BM;
  int hbase = blockIdx.y * 32;
  int tid = threadIdx.x;
  int wid = tid >> 5, lane = tid & 31;
  int wm = wid & 1, wn = wid >> 1;
  int g8 = lane >> 2, tg = lane & 3;

  for (int mt = blockIdx.x; mt < nmt; mt += gridDim.x) {
    __syncthreads();
    if (tid < BM) {
      int idx = mt*BM + tid;
      plist[tid] = (idx < count) ? g_lvllist[(size_t)L*BT + idx] : -1;
    }
    __syncthreads();

    float acc[2][4][4];
    #pragma unroll
    for (int i = 0; i < 2; i++)
      #pragma unroll
      for (int j = 0; j < 4; j++)
        #pragma unroll
        for (int q = 0; q < 4; q++) acc[i][j][q] = 0.0f;

    for (int kc = 0; kc < HQ; kc += BKC) {
      {
        int row = tid >> 2, q = tid & 3;
        int p = plist[row]; if (p < 0) p = 1;
        stage_a(SM, g_H + (size_t)(p-1)*HQ + kc + q*8, row, q);
      }
      {
        int c = tid >> 1, half = tid & 1;
        int j = (c & 3)*HQ + hbase + (c >> 2);
        stage_b(SM, W_hh + (size_t)j*HQ + kc + half*16, c, half);
      }
      __syncthreads();
      mma_block(SM, acc, wm, wn, lane);
      __syncthreads();
    }

    dump_es(Es, acc, wm, wn, g8, tg);
    __syncthreads();

    #pragma unroll
    for (int it = 0; it < 8; it++) {
      int item = it*256 + tid;
      int r = item >> 5, u = item & 31;
      int p = plist[r];
      if (p < 0) continue;
      int hu = hbase + u;
      int t = p & (TQ-1);
      int len = __ldg(&length[p >> 10]);
      float a = (t < len) ? 1.0f : 0.0f;
      int sf = (p + 1 < BT) ? (int)g_m[p+1] : 0;
      int em = g_emit[p];
      size_t pb = (size_t)p*G4 + hu;
      float4 gv = *(const float4*)(Es + r*ES_STR + 4*u);
      float vi = gv.x + g_pre[pb + 0*HQ];
      float vf = gv.y + g_pre[pb + 1*HQ];
      float vg = gv.z + g_pre[pb + 2*HQ];
      float vo = gv.w + g_pre[pb + 3*HQ];
      float hin = g_H[(size_t)(p-1)*HQ + hu];
      float cin = g_C[(size_t)(p-1)*HQ + hu];
      float c2 = sigf(vf)*cin + sigf(vi)*tanhf(vg);
      float h2 = sigf(vo)*tanhf(c2);
      float hv = a*h2 + (1.0f - a)*hin;
      float cv = a*c2 + (1.0f - a)*cin;
      if (sf) {
        g_H[(size_t)p*HQ + hu] = hv;
        g_C[(size_t)p*HQ + hu] = cv;
      }
      if (em >= 0) out[(size_t)em*HQ + hu] = a*h2;
    }
  }
}

extern "C" void kernel_launch(void* const* d_in, const int* in_sizes, int n_in,
                              void* d_out, int out_size) {
  const float* x      = (const float*)d_in[0];
  const int*   mask   = (const int*)d_in[1];
  const int*   length = (const int*)d_in[2];
  const float* W_ih   = (const float*)d_in[3];
  const float* W_hh   = (const float*)d_in[4];
  const float* b_ih   = (const float*)d_in[5];
  const float* b_hh   = (const float*)d_in[6];
  float* out = (float*)d_out;

  long long per = (long long)BQ * HQ;
  int K, has_wn;
  if ((long long)out_size % per == 0) { K = (int)((long long)out_size / per); has_wn = 0; }
  else { K = (int)(((long long)out_size - BQ) / per); has_wn = 1; }

  k_init<<<(BT + 255)/256, 256>>>();
  k_row<<<BQ, 32>>>(mask, length, out, K, has_wn);
  k_work<<<(BT + 255)/256, 256>>>();
  k_main<<<dim3(256, 16), 256>>>(x, length, W_ih, b_ih, b_hh, out);
  for (int L = 1; L <= MAXLEV; L++) {
    int gx = (L == 1) ? 192 : (L == 2) ? 32 : 4;
    k_level<<<dim3(gx, 16), 256>>>(W_hh, length, out, L);
  }
}